// round 12
// baseline (speedup 1.0000x reference)
#include <cuda_runtime.h>
#include <math.h>

#define BX 32
#define BY 8
#define TPT_X 4               // outputs per thread, x
#define TPT_Y 2               // outputs per thread, y
#define TILE_W (BX * TPT_X)   // 128
#define TILE_H (BY * TPT_Y)   // 16
#define SM_W (TILE_W + 4)     // 132
#define SM_H (TILE_H + 4)     // 20

__global__ __launch_bounds__(BX * BY)
void hitmiss_kernel(const float* __restrict__ in,
                    const float* __restrict__ Kh,
                    const float* __restrict__ Km,
                    float* __restrict__ out,
                    int H, int W, int Hout, int Wout)
{
    __shared__ __align__(16) float tile[SM_H][SM_W];   // 10.3 KB
    __shared__ __align__(16) float skh[5][8];          // padded tap rows (32B stride)
    __shared__ __align__(16) float skm[5][8];

    const int tid  = threadIdx.y * BX + threadIdx.x;
    const int col0 = blockIdx.x * TILE_W;
    const int row0 = blockIdx.y * TILE_H;

    const bool interior = (row0 + SM_H <= H) && (col0 + SM_W <= W);

    // stage taps into padded smem rows: per-di row is one aligned float4 + scalar
    if (tid < 25) {
        skh[tid / 5][tid % 5] = Kh[tid];
        skm[tid / 5][tid % 5] = Km[tid];
    }

    if (interior) {
        // --- fast loader: straight-line 2D indexing, all LDG.128 aligned ---
        const float* base = in + (size_t)row0 * W + col0;
        const int tx4 = threadIdx.x * 4;
#pragma unroll
        for (int i = 0; i < 2; ++i) {                 // rows 0..15
            const int r = threadIdx.y + 8 * i;
            *reinterpret_cast<float4*>(&tile[r][tx4]) =
                *reinterpret_cast<const float4*>(base + (size_t)r * W + tx4);
        }
        if (threadIdx.y < 4) {                        // rows 16..19
            const int r = 16 + threadIdx.y;
            *reinterpret_cast<float4*>(&tile[r][tx4]) =
                *reinterpret_cast<const float4*>(base + (size_t)r * W + tx4);
        }
        if (tid < SM_H) {                             // last float4 column (128..131)
            *reinterpret_cast<float4*>(&tile[tid][TILE_W]) =
                *reinterpret_cast<const float4*>(base + (size_t)tid * W + TILE_W);
        }
    } else {
        // --- boundary loader (rare): generic with clamps ---
        const int NW4 = SM_W / 4;          // 33
        const int NV  = NW4 * SM_H;        // 660 float4 slots
        for (int idx = tid; idx < NV; idx += BX * BY) {
            int r  = idx / NW4;
            int c4 = idx - r * NW4;
            int gr = row0 + r; if (gr > H - 1) gr = H - 1;
            int gc = col0 + c4 * 4;
            float4 v;
            if (gc + 3 <= W - 1) {
                v = *reinterpret_cast<const float4*>(in + (size_t)gr * W + gc);
            } else {
                int c0 = gc     < W - 1 ? gc     : W - 1;
                int c1 = gc + 1 < W - 1 ? gc + 1 : W - 1;
                int c2 = gc + 2 < W - 1 ? gc + 2 : W - 1;
                int c3 = gc + 3 < W - 1 ? gc + 3 : W - 1;
                const float* rowp = in + (size_t)gr * W;
                v.x = rowp[c0]; v.y = rowp[c1]; v.z = rowp[c2]; v.w = rowp[c3];
            }
            *reinterpret_cast<float4*>(&tile[r][c4 * 4]) = v;
        }
    }
    __syncthreads();

    // --- di-outer, rolling 3-row window: only 10 taps + 24 window floats live ---
    const int lx = threadIdx.x * TPT_X;   // multiple of 4 -> aligned LDS.128
    const int ly = threadIdx.y * TPT_Y;

    float w[3][8];                         // rotating row buffers
    {
        float4 a = *reinterpret_cast<const float4*>(&tile[ly + 0][lx]);
        float4 b = *reinterpret_cast<const float4*>(&tile[ly + 0][lx + 4]);
        w[0][0]=a.x; w[0][1]=a.y; w[0][2]=a.z; w[0][3]=a.w;
        w[0][4]=b.x; w[0][5]=b.y; w[0][6]=b.z; w[0][7]=b.w;
        float4 c = *reinterpret_cast<const float4*>(&tile[ly + 1][lx]);
        float4 d = *reinterpret_cast<const float4*>(&tile[ly + 1][lx + 4]);
        w[1][0]=c.x; w[1][1]=c.y; w[1][2]=c.z; w[1][3]=c.w;
        w[1][4]=d.x; w[1][5]=d.y; w[1][6]=d.z; w[1][7]=d.w;
    }

    float mn[TPT_Y][TPT_X], mx[TPT_Y][TPT_X];

#pragma unroll
    for (int di = 0; di < 5; ++di) {
        // prefetch row ly+di+2 into the dead buffer (hides LDS latency under compute)
        if (di < 4) {
            float4 a = *reinterpret_cast<const float4*>(&tile[ly + di + 2][lx]);
            float4 b = *reinterpret_cast<const float4*>(&tile[ly + di + 2][lx + 4]);
            float* dst = w[(di + 2) % 3];
            dst[0]=a.x; dst[1]=a.y; dst[2]=a.z; dst[3]=a.w;
            dst[4]=b.x; dst[5]=b.y; dst[6]=b.z; dst[7]=b.w;
        }

        // tap row di: 2 broadcast LDS per kernel (all lanes same address, N=1)
        float4 kh4 = *reinterpret_cast<const float4*>(&skh[di][0]);
        float  khE = skh[di][4];
        float4 km4 = *reinterpret_cast<const float4*>(&skm[di][0]);
        float  kmE = skm[di][4];
        const float khr[5] = {kh4.x, kh4.y, kh4.z, kh4.w, khE};
        const float kmr[5] = {km4.x, km4.y, km4.z, km4.w, kmE};

        const float* wA = w[di % 3];          // row ly+di   -> orow 0
        const float* wB = w[(di + 1) % 3];    // row ly+di+1 -> orow 1

#pragma unroll
        for (int orow = 0; orow < TPT_Y; ++orow) {
            const float* ww = orow ? wB : wA;
#pragma unroll
            for (int oc = 0; oc < TPT_X; ++oc) {
                float h0 = ww[oc + 0] - khr[0];
                float h1 = ww[oc + 1] - khr[1];
                float h2 = ww[oc + 2] - khr[2];
                float h3 = ww[oc + 3] - khr[3];
                float h4 = ww[oc + 4] - khr[4];
                float m0 = ww[oc + 0] - kmr[0];
                float m1 = ww[oc + 1] - kmr[1];
                float m2 = ww[oc + 2] - kmr[2];
                float m3 = ww[oc + 3] - kmr[3];
                float m4 = ww[oc + 4] - kmr[4];

                if (di == 0) {
                    // 5 -> 1 in exactly 2 fused ops (FMNMX3 + FMNMX3)
                    mn[orow][oc] = fminf(fminf(fminf(fminf(h0, h1), h2), h3), h4);
                    mx[orow][oc] = fmaxf(fmaxf(fmaxf(fmaxf(m0, m1), m2), m3), m4);
                } else {
                    // 6 -> 1: two FMNMX3 + merge
                    float tA = fminf(fminf(h0, h1), h2);
                    float tB = fminf(fminf(h3, h4), mn[orow][oc]);
                    mn[orow][oc] = fminf(tA, tB);
                    float uA = fmaxf(fmaxf(m0, m1), m2);
                    float uB = fmaxf(fmaxf(m3, m4), mx[orow][oc]);
                    mx[orow][oc] = fmaxf(uA, uB);
                }
            }
        }
    }

    // --- stores ---
    const int oc0 = col0 + lx;
    const int or0 = row0 + ly;
    if (interior && (oc0 + 3 < Wout) && (or0 + TPT_Y <= Hout)) {
        float* p = out + (size_t)or0 * Wout + oc0;
#pragma unroll
        for (int orow = 0; orow < TPT_Y; ++orow) {
            float4 o;
            o.x = mn[orow][0] - mx[orow][0];
            o.y = mn[orow][1] - mx[orow][1];
            o.z = mn[orow][2] - mx[orow][2];
            o.w = mn[orow][3] - mx[orow][3];
            *reinterpret_cast<float4*>(p) = o;
            p += Wout;
        }
    } else {
#pragma unroll
        for (int orow = 0; orow < TPT_Y; ++orow) {
            const int gro = or0 + orow;
            if (gro >= Hout) continue;
            float r0 = mn[orow][0] - mx[orow][0];
            float r1 = mn[orow][1] - mx[orow][1];
            float r2 = mn[orow][2] - mx[orow][2];
            float r3 = mn[orow][3] - mx[orow][3];
            float* orow_p = out + (size_t)gro * Wout;
            if (oc0 + 0 < Wout) orow_p[oc0 + 0] = r0;
            if (oc0 + 1 < Wout) orow_p[oc0 + 1] = r1;
            if (oc0 + 2 < Wout) orow_p[oc0 + 2] = r2;
            if (oc0 + 3 < Wout) orow_p[oc0 + 3] = r3;
        }
    }
}

extern "C" void kernel_launch(void* const* d_in, const int* in_sizes, int n_in,
                              void* d_out, int out_size)
{
    const float* in = (const float*)d_in[0];
    const float* Kh = (const float*)d_in[1];
    const float* Km = (const float*)d_in[2];
    float* out = (float*)d_out;

    const int H = (int)lround(sqrt((double)in_sizes[0]));
    const int W = H;
    const int Hout = H - 4;
    const int Wout = W - 4;

    dim3 block(BX, BY);
    dim3 grid((Wout + TILE_W - 1) / TILE_W, (Hout + TILE_H - 1) / TILE_H);
    hitmiss_kernel<<<grid, block>>>(in, Kh, Km, out, H, W, Hout, Wout);
}

// round 13
// speedup vs baseline: 1.1893x; 1.1893x over previous
#include <cuda_runtime.h>
#include <math.h>

#define BX 32
#define BY 4
#define TPT_X 4               // outputs per thread, x
#define TPT_Y 4               // outputs per thread, y
#define TILE_W (BX * TPT_X)   // 128
#define TILE_H (BY * TPT_Y)   // 16
#define SM_W (TILE_W + 4)     // 132
#define SM_H (TILE_H + 4)     // 20

__global__ __launch_bounds__(BX * BY)
void hitmiss_kernel(const float* __restrict__ in,
                    const float* __restrict__ Kh,
                    const float* __restrict__ Km,
                    float* __restrict__ out,
                    int H, int W, int Hout, int Wout)
{
    __shared__ __align__(16) float tile[SM_H][SM_W];   // 10.3 KB

    const int tid  = threadIdx.y * BX + threadIdx.x;
    const int col0 = blockIdx.x * TILE_W;
    const int row0 = blockIdx.y * TILE_H;

    const bool interior = (row0 + SM_H <= H) && (col0 + SM_W <= W);

    // --- taps via vectorized broadcast loads: 13 LDG instead of 50 ---
    float kh[25], km[25];
    {
        const float4* Kh4 = reinterpret_cast<const float4*>(Kh);
        const float4* Km4 = reinterpret_cast<const float4*>(Km);
#pragma unroll
        for (int i = 0; i < 6; ++i) {
            float4 a = __ldg(Kh4 + i);
            kh[4*i+0] = a.x; kh[4*i+1] = a.y; kh[4*i+2] = a.z; kh[4*i+3] = a.w;
            float4 b = __ldg(Km4 + i);
            km[4*i+0] = b.x; km[4*i+1] = b.y; km[4*i+2] = b.z; km[4*i+3] = b.w;
        }
        kh[24] = __ldg(Kh + 24);
        km[24] = __ldg(Km + 24);
    }

    if (interior) {
        // --- fast loader: straight-line 2D indexing, all LDG.128 aligned ---
        const float* base = in + (size_t)row0 * W + col0;
        const int tx4 = threadIdx.x * 4;
#pragma unroll
        for (int i = 0; i < 4; ++i) {                 // rows 0..15
            const int r = threadIdx.y + 4 * i;
            *reinterpret_cast<float4*>(&tile[r][tx4]) =
                *reinterpret_cast<const float4*>(base + (size_t)r * W + tx4);
        }
        {                                             // rows 16..19 (all ty lanes)
            const int r = 16 + threadIdx.y;
            *reinterpret_cast<float4*>(&tile[r][tx4]) =
                *reinterpret_cast<const float4*>(base + (size_t)r * W + tx4);
        }
        if (tid < SM_H) {                             // last float4 column (128..131)
            *reinterpret_cast<float4*>(&tile[tid][TILE_W]) =
                *reinterpret_cast<const float4*>(base + (size_t)tid * W + TILE_W);
        }
    } else {
        // --- boundary loader (rare): generic with clamps ---
        const int NW4 = SM_W / 4;          // 33
        const int NV  = NW4 * SM_H;        // 660 float4 slots
        for (int idx = tid; idx < NV; idx += BX * BY) {
            int r  = idx / NW4;
            int c4 = idx - r * NW4;
            int gr = row0 + r; if (gr > H - 1) gr = H - 1;
            int gc = col0 + c4 * 4;
            float4 v;
            if (gc + 3 <= W - 1) {
                v = *reinterpret_cast<const float4*>(in + (size_t)gr * W + gc);
            } else {
                int c0 = gc     < W - 1 ? gc     : W - 1;
                int c1 = gc + 1 < W - 1 ? gc + 1 : W - 1;
                int c2 = gc + 2 < W - 1 ? gc + 2 : W - 1;
                int c3 = gc + 3 < W - 1 ? gc + 3 : W - 1;
                const float* rowp = in + (size_t)gr * W;
                v.x = rowp[c0]; v.y = rowp[c1]; v.z = rowp[c2]; v.w = rowp[c3];
            }
            *reinterpret_cast<float4*>(&tile[r][c4 * 4]) = v;
        }
    }
    __syncthreads();

    // --- 4x4 register-blocked hit-or-miss, row-streaming, FMNMX3 trees ---
    const int lx = threadIdx.x * TPT_X;   // multiple of 4 -> aligned LDS.128
    const int ly = threadIdx.y * TPT_Y;

    float mn[TPT_Y * TPT_X], mx[TPT_Y * TPT_X];

#pragma unroll
    for (int r = 0; r < TPT_Y + 4; ++r) {          // 8 input rows
        float w[TPT_X + 4];
        float4 a = *reinterpret_cast<const float4*>(&tile[ly + r][lx]);
        float4 b = *reinterpret_cast<const float4*>(&tile[ly + r][lx + 4]);
        w[0] = a.x; w[1] = a.y; w[2] = a.z; w[3] = a.w;
        w[4] = b.x; w[5] = b.y; w[6] = b.z; w[7] = b.w;

#pragma unroll
        for (int orow = 0; orow < TPT_Y; ++orow) {
            const int di = r - orow;
            if (di < 0 || di > 4) continue;          // compile-time pruned
#pragma unroll
            for (int oc = 0; oc < TPT_X; ++oc) {
                const int o = orow * TPT_X + oc;

                float h0 = w[oc + 0] - kh[di * 5 + 0];
                float h1 = w[oc + 1] - kh[di * 5 + 1];
                float h2 = w[oc + 2] - kh[di * 5 + 2];
                float h3 = w[oc + 3] - kh[di * 5 + 3];
                float h4 = w[oc + 4] - kh[di * 5 + 4];
                float m0 = w[oc + 0] - km[di * 5 + 0];
                float m1 = w[oc + 1] - km[di * 5 + 1];
                float m2 = w[oc + 2] - km[di * 5 + 2];
                float m3 = w[oc + 3] - km[di * 5 + 3];
                float m4 = w[oc + 4] - km[di * 5 + 4];

                if (di == 0) {
                    // 5 -> 1 in exactly 2 fused ops (FMNMX3 + FMNMX3)
                    mn[o] = fminf(fminf(fminf(fminf(h0, h1), h2), h3), h4);
                    mx[o] = fmaxf(fmaxf(fmaxf(fmaxf(m0, m1), m2), m3), m4);
                } else {
                    // 6 -> 1: two FMNMX3 + merge
                    float tA = fminf(fminf(h0, h1), h2);       // FMNMX3
                    float tB = fminf(fminf(h3, h4), mn[o]);    // FMNMX3
                    mn[o] = fminf(tA, tB);
                    float uA = fmaxf(fmaxf(m0, m1), m2);       // FMNMX3
                    float uB = fmaxf(fmaxf(m3, m4), mx[o]);    // FMNMX3
                    mx[o] = fmaxf(uA, uB);
                }
            }
        }
    }

    // --- stores ---
    const int oc0 = col0 + lx;
    const int or0 = row0 + ly;
    if (interior && (oc0 + 3 < Wout) && (or0 + TPT_Y <= Hout)) {
        float* p = out + (size_t)or0 * Wout + oc0;
#pragma unroll
        for (int orow = 0; orow < TPT_Y; ++orow) {
            float4 o;
            o.x = mn[orow * TPT_X + 0] - mx[orow * TPT_X + 0];
            o.y = mn[orow * TPT_X + 1] - mx[orow * TPT_X + 1];
            o.z = mn[orow * TPT_X + 2] - mx[orow * TPT_X + 2];
            o.w = mn[orow * TPT_X + 3] - mx[orow * TPT_X + 3];
            *reinterpret_cast<float4*>(p) = o;
            p += Wout;
        }
    } else {
#pragma unroll
        for (int orow = 0; orow < TPT_Y; ++orow) {
            const int gro = or0 + orow;
            if (gro >= Hout) continue;
            float r0 = mn[orow * TPT_X + 0] - mx[orow * TPT_X + 0];
            float r1 = mn[orow * TPT_X + 1] - mx[orow * TPT_X + 1];
            float r2 = mn[orow * TPT_X + 2] - mx[orow * TPT_X + 2];
            float r3 = mn[orow * TPT_X + 3] - mx[orow * TPT_X + 3];
            float* orow_p = out + (size_t)gro * Wout;
            if (oc0 + 0 < Wout) orow_p[oc0 + 0] = r0;
            if (oc0 + 1 < Wout) orow_p[oc0 + 1] = r1;
            if (oc0 + 2 < Wout) orow_p[oc0 + 2] = r2;
            if (oc0 + 3 < Wout) orow_p[oc0 + 3] = r3;
        }
    }
}

extern "C" void kernel_launch(void* const* d_in, const int* in_sizes, int n_in,
                              void* d_out, int out_size)
{
    const float* in = (const float*)d_in[0];
    const float* Kh = (const float*)d_in[1];
    const float* Km = (const float*)d_in[2];
    float* out = (float*)d_out;

    const int H = (int)lround(sqrt((double)in_sizes[0]));
    const int W = H;
    const int Hout = H - 4;
    const int Wout = W - 4;

    dim3 block(BX, BY);
    dim3 grid((Wout + TILE_W - 1) / TILE_W, (Hout + TILE_H - 1) / TILE_H);
    hitmiss_kernel<<<grid, block>>>(in, Kh, Km, out, H, W, Hout, Wout);
}